// round 15
// baseline (speedup 1.0000x reference)
#include <cuda_runtime.h>
#include <cuda_fp16.h>

#define D 256
#define MAXN 50048
#define MAXE 400256
#define LN_EPS 1e-5f
#define MAXSLOT 96

// ---------------- scratch (static device globals; no allocation) ------------
__device__ __half  g_w16t[D * D];          // (W0+W1+W2)/3, TRANSPOSED [n][k], fp16
__device__ __half  g_afeat16[MAXN * D];    // aggregated features, fp16 (GEMM A)
__device__ __half2 g_feat16[MAXN * D / 2]; // fp16 copy of feat for the gather
__device__ int     g_deg[3 * MAXN];        // zero-initialized; agg resets after use
__device__ int     g_bucket[MAXSLOT * 3 * MAXN];  // slot-major: [slot][relNode]

// ---------------- conversion: feat->fp16, Wsum^T->fp16 (side stream) --------
__global__ void conv_kernel(const float* __restrict__ feat,
                            const float* __restrict__ W0,
                            const float* __restrict__ W1,
                            const float* __restrict__ W2,
                            int total2) {
    int i = blockIdx.x * blockDim.x + threadIdx.x;
    if (i < total2) {
        float2 v = ((const float2*)feat)[i];
        g_feat16[i] = __floats2half2_rn(v.x, v.y);
    }
    if (i < D * D) {
        int k = i >> 8, n = i & 255;
        float v = (W0[i] + W1[i] + W2[i]) * (1.0f / 3.0f);
        g_w16t[n * D + k] = __float2half_rn(v);
    }
}

// ---------------- scatter: direct slot assignment (deg starts at zero) -------
__global__ void scatter_kernel(const int* __restrict__ s0, const int* __restrict__ d0,
                               const int* __restrict__ s1, const int* __restrict__ d1,
                               const int* __restrict__ s2, const int* __restrict__ d2,
                               int N, int E) {
    int base = (blockIdx.x * blockDim.x + threadIdx.x) * 4;
    int totalN = 3 * N;
    #pragma unroll
    for (int u = 0; u < 4; u++) {
        int i = base + u;
        if (i >= 3 * E) break;
        int r = i / E, e = i - r * E;
        const int* ss = (r == 0) ? s0 : (r == 1) ? s1 : s2;
        const int* ds = (r == 0) ? d0 : (r == 1) ? d1 : d2;
        int idx = r * N + ds[e];
        int p = atomicAdd(&g_deg[idx], 1);
        if (p < MAXSLOT)
            g_bucket[(size_t)p * totalN + idx] = ss[e];
    }
}

// ---------------- aggregate: warp/node, paired HADD2 + fp32 accumulate ------
// Processes edges in pairs: rows combined with 4x HADD2, then ONE convert+add
// to fp32 per pair (halves the F2F/FADD stream, the issue-bound hot path).
// Resets g_deg after use so no separate zero pass is needed.
__global__ __launch_bounds__(256) void agg_kernel(int N) {
    int gwarp = (blockIdx.x * blockDim.x + threadIdx.x) >> 5;
    int lane = threadIdx.x & 31;
    if (gwarp >= N) return;
    size_t totalN = 3 * (size_t)N;

    float acc[8] = {0.f, 0.f, 0.f, 0.f, 0.f, 0.f, 0.f, 0.f};
    #pragma unroll
    for (int r = 0; r < 3; r++) {
        int idx = r * N + gwarp;
        int dg = min(g_deg[idx], MAXSLOT);
        float s[8] = {0.f, 0.f, 0.f, 0.f, 0.f, 0.f, 0.f, 0.f};
        int e = 0;
        for (; e + 1 < dg; e += 2) {
            int srcA = g_bucket[(size_t)e * totalN + idx];
            int srcB = g_bucket[(size_t)(e + 1) * totalN + idx];
            int4 va = *((const int4*)(g_feat16 + (size_t)srcA * (D / 2)) + lane);
            int4 vb = *((const int4*)(g_feat16 + (size_t)srcB * (D / 2)) + lane);
            __half2 p0 = __hadd2(*(__half2*)&va.x, *(__half2*)&vb.x);
            __half2 p1 = __hadd2(*(__half2*)&va.y, *(__half2*)&vb.y);
            __half2 p2 = __hadd2(*(__half2*)&va.z, *(__half2*)&vb.z);
            __half2 p3 = __hadd2(*(__half2*)&va.w, *(__half2*)&vb.w);
            float2 f0 = __half22float2(p0);
            float2 f1 = __half22float2(p1);
            float2 f2 = __half22float2(p2);
            float2 f3 = __half22float2(p3);
            s[0] += f0.x; s[1] += f0.y; s[2] += f1.x; s[3] += f1.y;
            s[4] += f2.x; s[5] += f2.y; s[6] += f3.x; s[7] += f3.y;
        }
        if (e < dg) {
            int src = g_bucket[(size_t)e * totalN + idx];
            int4 v = *((const int4*)(g_feat16 + (size_t)src * (D / 2)) + lane);
            float2 f0 = __half22float2(*(__half2*)&v.x);
            float2 f1 = __half22float2(*(__half2*)&v.y);
            float2 f2 = __half22float2(*(__half2*)&v.z);
            float2 f3 = __half22float2(*(__half2*)&v.w);
            s[0] += f0.x; s[1] += f0.y; s[2] += f1.x; s[3] += f1.y;
            s[4] += f2.x; s[5] += f2.y; s[6] += f3.x; s[7] += f3.y;
        }
        float sc = 1.0f / fmaxf((float)dg, 1.0f);
        #pragma unroll
        for (int k = 0; k < 8; k++) acc[k] += s[k] * sc;
    }
    // reset degree counters for the next replay (loop above is warp-uniform,
    // so all reads of g_deg precede these writes in program order)
    if (lane < 3) g_deg[lane * N + gwarp] = 0;

    const float third = 1.0f / 3.0f;
    __half2 o[4];
    #pragma unroll
    for (int k = 0; k < 4; k++)
        o[k] = __floats2half2_rn(acc[2 * k] * third, acc[2 * k + 1] * third);
    int4* orow = (int4*)(g_afeat16 + (size_t)gwarp * D + lane * 8);
    *orow = *(int4*)o;
}

// ---------------- tensor-core GEMM + ReLU + LayerNorm ------------------------
// Full A-tile (128x256) and B (256x256) resident in smem; ONE sync, then
// 16 uninterrupted MMA k-steps. Block: 128 rows, 512 threads, 16 warps.
#define RST 264
#define GEMM_SMEM (((128 + 256) * RST) * 2 + 2 * 8 * 16 * 8)

__device__ __forceinline__ void mma16816(float* d, const unsigned* a,
                                         const unsigned* b, const float* c) {
    asm volatile(
        "mma.sync.aligned.m16n8k16.row.col.f32.f16.f16.f32 "
        "{%0,%1,%2,%3}, {%4,%5,%6,%7}, {%8,%9}, {%10,%11,%12,%13};\n"
        : "=f"(d[0]), "=f"(d[1]), "=f"(d[2]), "=f"(d[3])
        : "r"(a[0]), "r"(a[1]), "r"(a[2]), "r"(a[3]),
          "r"(b[0]), "r"(b[1]),
          "f"(c[0]), "f"(c[1]), "f"(c[2]), "f"(c[3]));
}

__global__ __launch_bounds__(512) void gemm_ln_tc(const float* __restrict__ gamma,
                                                  const float* __restrict__ beta,
                                                  float* __restrict__ out, int M) {
    extern __shared__ __half smem[];
    __half* As = smem;                          // 128 x RST
    __half* Bs = smem + 128 * RST;              // 256 x RST
    float2* sred = (float2*)(smem + (128 + 256) * RST);  // [2][8][16]

    int tid = threadIdx.x;
    int wid = tid >> 5;
    int lane = tid & 31;
    int g = lane >> 2;
    int t = lane & 3;
    int mchunk = wid & 7;
    int nhalf = wid >> 3;
    int rowBase = blockIdx.x * 128;

    #pragma unroll
    for (int j = 0; j < 8; j++) {
        int l = tid + 512 * j;
        int row = l >> 5;
        int unit = l & 31;
        int4 v = make_int4(0, 0, 0, 0);
        if (rowBase + row < M)
            v = *(const int4*)(g_afeat16 + (size_t)(rowBase + row) * D + unit * 8);
        *(int4*)&As[row * RST + unit * 8] = v;
    }
    #pragma unroll
    for (int j = 0; j < 16; j++) {
        int l = tid + 512 * j;
        int row = l >> 5;
        int unit = l & 31;
        *(int4*)&Bs[row * RST + unit * 8] =
            *(const int4*)(g_w16t + (size_t)row * D + unit * 8);
    }
    __syncthreads();

    float cacc[16][4];
    #pragma unroll
    for (int i = 0; i < 16; i++)
        #pragma unroll
        for (int j = 0; j < 4; j++) cacc[i][j] = 0.f;

    const __half* ab = &As[(mchunk * 16) * RST];
    #pragma unroll
    for (int kc = 0; kc < 16; kc++) {
        int kh = kc * 16;
        unsigned a[4];
        a[0] = *(const unsigned*)&ab[g * RST + kh + 2 * t];
        a[1] = *(const unsigned*)&ab[(g + 8) * RST + kh + 2 * t];
        a[2] = *(const unsigned*)&ab[g * RST + kh + 2 * t + 8];
        a[3] = *(const unsigned*)&ab[(g + 8) * RST + kh + 2 * t + 8];
        #pragma unroll
        for (int nt = 0; nt < 16; nt++) {
            int n = nhalf * 128 + nt * 8 + g;
            unsigned b[2];
            b[0] = *(const unsigned*)&Bs[n * RST + kh + 2 * t];
            b[1] = *(const unsigned*)&Bs[n * RST + kh + 2 * t + 8];
            mma16816(cacc[nt], a, b, cacc[nt]);
        }
    }

    float s0 = 0.f, ss0 = 0.f, s1 = 0.f, ss1 = 0.f;
    #pragma unroll
    for (int nt = 0; nt < 16; nt++) {
        float c0 = fmaxf(cacc[nt][0], 0.f);
        float c1 = fmaxf(cacc[nt][1], 0.f);
        float c2 = fmaxf(cacc[nt][2], 0.f);
        float c3 = fmaxf(cacc[nt][3], 0.f);
        cacc[nt][0] = c0; cacc[nt][1] = c1; cacc[nt][2] = c2; cacc[nt][3] = c3;
        s0 += c0 + c1; ss0 += c0 * c0 + c1 * c1;
        s1 += c2 + c3; ss1 += c2 * c2 + c3 * c3;
    }
    #pragma unroll
    for (int o = 1; o <= 2; o <<= 1) {
        s0 += __shfl_xor_sync(0xffffffffu, s0, o);
        ss0 += __shfl_xor_sync(0xffffffffu, ss0, o);
        s1 += __shfl_xor_sync(0xffffffffu, s1, o);
        ss1 += __shfl_xor_sync(0xffffffffu, ss1, o);
    }
    if (t == 0) {
        sred[(nhalf * 8 + mchunk) * 16 + g] = make_float2(s0, ss0);
        sred[(nhalf * 8 + mchunk) * 16 + g + 8] = make_float2(s1, ss1);
    }
    __syncthreads();
    float2 u0 = sred[(0 * 8 + mchunk) * 16 + g];
    float2 v0 = sred[(1 * 8 + mchunk) * 16 + g];
    float2 u1 = sred[(0 * 8 + mchunk) * 16 + g + 8];
    float2 v1 = sred[(1 * 8 + mchunk) * 16 + g + 8];
    float mu0 = (u0.x + v0.x) * (1.0f / D);
    float var0 = (u0.y + v0.y) * (1.0f / D) - mu0 * mu0;
    float rs0 = rsqrtf(var0 + LN_EPS);
    float mu1 = (u1.x + v1.x) * (1.0f / D);
    float var1 = (u1.y + v1.y) * (1.0f / D) - mu1 * mu1;
    float rs1 = rsqrtf(var1 + LN_EPS);

    int gr0 = rowBase + mchunk * 16 + g;
    int gr1 = gr0 + 8;
    #pragma unroll
    for (int nt = 0; nt < 16; nt++) {
        int col = nhalf * 128 + nt * 8 + 2 * t;
        float2 gm = *(const float2*)(gamma + col);
        float2 bt = *(const float2*)(beta + col);
        if (gr0 < M) {
            float2 o0;
            o0.x = (cacc[nt][0] - mu0) * rs0 * gm.x + bt.x;
            o0.y = (cacc[nt][1] - mu0) * rs0 * gm.y + bt.y;
            *(float2*)(out + (size_t)gr0 * D + col) = o0;
        }
        if (gr1 < M) {
            float2 o1;
            o1.x = (cacc[nt][2] - mu1) * rs1 * gm.x + bt.x;
            o1.y = (cacc[nt][3] - mu1) * rs1 * gm.y + bt.y;
            *(float2*)(out + (size_t)gr1 * D + col) = o1;
        }
    }
}

// ---------------- launch ----------------------------------------------------
extern "C" void kernel_launch(void* const* d_in, const int* in_sizes, int n_in,
                              void* d_out, int out_size) {
    const float* feat = (const float*)d_in[0];
    const float* W0 = (const float*)d_in[1];
    const float* W1 = (const float*)d_in[2];
    const float* W2 = (const float*)d_in[3];
    // d_in[4..6] = a0,a1,a2: softmax over size-1 tensors is identically 1,
    // so the mixing weights are always [1/3,1/3,1/3] independent of values.
    const float* gamma = (const float*)d_in[7];
    const float* beta = (const float*)d_in[8];
    const int* src0 = (const int*)d_in[9];
    const int* dst0 = (const int*)d_in[10];
    const int* src1 = (const int*)d_in[11];
    const int* dst1 = (const int*)d_in[12];
    const int* src2 = (const int*)d_in[13];
    const int* dst2 = (const int*)d_in[14];
    float* out = (float*)d_out;

    int N = in_sizes[0] / D;
    int E = in_sizes[9];
    int total2 = N * D / 2;

    static cudaStream_t s_conv = nullptr;
    static cudaEvent_t s_fork = nullptr, s_evC = nullptr;
    if (s_conv == nullptr) {
        cudaStreamCreateWithFlags(&s_conv, cudaStreamNonBlocking);
        cudaEventCreateWithFlags(&s_fork, cudaEventDisableTiming);
        cudaEventCreateWithFlags(&s_evC, cudaEventDisableTiming);
        cudaFuncSetAttribute(gemm_ln_tc,
                             cudaFuncAttributeMaxDynamicSharedMemorySize, GEMM_SMEM);
    }

    // fork: fp16 conversions run concurrently with the bucket build
    cudaEventRecord(s_fork, 0);
    cudaStreamWaitEvent(s_conv, s_fork, 0);
    conv_kernel<<<(total2 + 255) / 256, 256, 0, s_conv>>>(feat, W0, W1, W2, total2);
    cudaEventRecord(s_evC, s_conv);

    // deg starts zero (static init on first call, agg resets it every call)
    scatter_kernel<<<(3 * E + 1023) / 1024, 256>>>(src0, dst0, src1, dst1,
                                                   src2, dst2, N, E);

    // join conv, then aggregate + GEMM
    cudaStreamWaitEvent(0, s_evC, 0);
    agg_kernel<<<(N + 7) / 8, 256>>>(N);
    gemm_ln_tc<<<(N + 127) / 128, 512, GEMM_SMEM>>>(gamma, beta, out, N);
}

// round 17
// speedup vs baseline: 1.0171x; 1.0171x over previous
#include <cuda_runtime.h>
#include <cuda_fp16.h>
#include <cstdint>

#define D 256
#define MAXN 50048
#define MAXE 400256
#define LN_EPS 1e-5f
#define MAXSLOT 96

// ---------------- scratch (static device globals; no allocation) ------------
__device__ __half  g_w16t[D * D];          // (W0+W1+W2)/3, TRANSPOSED [n][k], fp16
__device__ __half  g_afeat16[MAXN * D];    // aggregated features, fp16 (GEMM A)
__device__ __half2 g_feat16[MAXN * D / 2]; // fp16 copy of feat for the gather
__device__ int     g_deg[3 * MAXN];        // zero-init; agg resets after use
__device__ int     g_bucket[MAXSLOT * 3 * MAXN];  // slot-major: [slot][relNode]

__device__ __forceinline__ uint32_t smem_u32(const void* p) {
    uint32_t a;
    asm("{ .reg .u64 t; cvta.to.shared.u64 t, %1; cvt.u32.u64 %0, t; }"
        : "=r"(a) : "l"(p));
    return a;
}

// ---------------- conversion: feat->fp16, Wsum^T->fp16 (side stream) --------
__global__ void conv_kernel(const float* __restrict__ feat,
                            const float* __restrict__ W0,
                            const float* __restrict__ W1,
                            const float* __restrict__ W2,
                            int total2) {
    int i = blockIdx.x * blockDim.x + threadIdx.x;
    if (i < total2) {
        float2 v = ((const float2*)feat)[i];
        g_feat16[i] = __floats2half2_rn(v.x, v.y);
    }
    if (i < D * D) {
        int k = i >> 8, n = i & 255;
        float v = (W0[i] + W1[i] + W2[i]) * (1.0f / 3.0f);
        g_w16t[n * D + k] = __float2half_rn(v);
    }
}

// ---------------- scatter: direct slot assignment (deg starts at zero) -------
__global__ void scatter_kernel(const int* __restrict__ s0, const int* __restrict__ d0,
                               const int* __restrict__ s1, const int* __restrict__ d1,
                               const int* __restrict__ s2, const int* __restrict__ d2,
                               int N, int E) {
    int base = (blockIdx.x * blockDim.x + threadIdx.x) * 4;
    int totalN = 3 * N;
    #pragma unroll
    for (int u = 0; u < 4; u++) {
        int i = base + u;
        if (i >= 3 * E) break;
        int r = i / E, e = i - r * E;
        const int* ss = (r == 0) ? s0 : (r == 1) ? s1 : s2;
        const int* ds = (r == 0) ? d0 : (r == 1) ? d1 : d2;
        int idx = r * N + ds[e];
        int p = atomicAdd(&g_deg[idx], 1);
        if (p < MAXSLOT)
            g_bucket[(size_t)p * totalN + idx] = ss[e];
    }
}

// ---------------- aggregate: warp per node, depth-2 pipelined gather ---------
__global__ __launch_bounds__(256) void agg_kernel(int N) {
    int gwarp = (blockIdx.x * blockDim.x + threadIdx.x) >> 5;
    int lane = threadIdx.x & 31;
    if (gwarp >= N) return;
    size_t totalN = 3 * (size_t)N;

    float acc[8] = {0.f, 0.f, 0.f, 0.f, 0.f, 0.f, 0.f, 0.f};
    #pragma unroll
    for (int r = 0; r < 3; r++) {
        int idx = r * N + gwarp;
        int dg = min(g_deg[idx], MAXSLOT);
        float s[8] = {0.f, 0.f, 0.f, 0.f, 0.f, 0.f, 0.f, 0.f};
        if (dg > 0) {
            int src = g_bucket[idx];
            int4 v = *((const int4*)(g_feat16 + (size_t)src * (D / 2)) + lane);
            for (int e = 1; e < dg; e++) {
                int src2 = g_bucket[(size_t)e * totalN + idx];
                int4 v2 = *((const int4*)(g_feat16 + (size_t)src2 * (D / 2)) + lane);
                float2 f0 = __half22float2(*(__half2*)&v.x);
                float2 f1 = __half22float2(*(__half2*)&v.y);
                float2 f2 = __half22float2(*(__half2*)&v.z);
                float2 f3 = __half22float2(*(__half2*)&v.w);
                s[0] += f0.x; s[1] += f0.y; s[2] += f1.x; s[3] += f1.y;
                s[4] += f2.x; s[5] += f2.y; s[6] += f3.x; s[7] += f3.y;
                v = v2;
            }
            float2 f0 = __half22float2(*(__half2*)&v.x);
            float2 f1 = __half22float2(*(__half2*)&v.y);
            float2 f2 = __half22float2(*(__half2*)&v.z);
            float2 f3 = __half22float2(*(__half2*)&v.w);
            s[0] += f0.x; s[1] += f0.y; s[2] += f1.x; s[3] += f1.y;
            s[4] += f2.x; s[5] += f2.y; s[6] += f3.x; s[7] += f3.y;
        }
        float sc = 1.0f / fmaxf((float)dg, 1.0f);
        #pragma unroll
        for (int k = 0; k < 8; k++) acc[k] += s[k] * sc;
    }
    // reset degree counters for next replay (reads above are warp-uniform)
    if (lane < 3) g_deg[lane * N + gwarp] = 0;

    const float third = 1.0f / 3.0f;
    __half2 o[4];
    #pragma unroll
    for (int k = 0; k < 4; k++)
        o[k] = __floats2half2_rn(acc[2 * k] * third, acc[2 * k + 1] * third);
    int4* orow = (int4*)(g_afeat16 + (size_t)gwarp * D + lane * 8);
    *orow = *(int4*)o;
}

// ---------------- tensor-core GEMM + ReLU + LayerNorm ------------------------
// Full A-tile (128x256) and B (256x256) resident in smem; ONE sync, then
// 16 MMA k-steps with ldmatrix.x4 fragment loads (9 LDSM vs 36 LDS per warp
// per k-step). Block: 128 rows, 512 threads, 16 warps.
#define RST 264
#define GEMM_SMEM (((128 + 256) * RST) * 2 + 2 * 8 * 16 * 8)

__device__ __forceinline__ void mma16816(float* d, const unsigned* a,
                                         unsigned b0, unsigned b1, const float* c) {
    asm volatile(
        "mma.sync.aligned.m16n8k16.row.col.f32.f16.f16.f32 "
        "{%0,%1,%2,%3}, {%4,%5,%6,%7}, {%8,%9}, {%10,%11,%12,%13};\n"
        : "=f"(d[0]), "=f"(d[1]), "=f"(d[2]), "=f"(d[3])
        : "r"(a[0]), "r"(a[1]), "r"(a[2]), "r"(a[3]),
          "r"(b0), "r"(b1),
          "f"(c[0]), "f"(c[1]), "f"(c[2]), "f"(c[3]));
}

#define LDSM_X4(r0, r1, r2, r3, addr)                                          \
    asm volatile("ldmatrix.sync.aligned.m8n8.x4.shared.b16 {%0,%1,%2,%3}, [%4];" \
                 : "=r"(r0), "=r"(r1), "=r"(r2), "=r"(r3) : "r"(addr))

__global__ __launch_bounds__(512) void gemm_ln_tc(const float* __restrict__ gamma,
                                                  const float* __restrict__ beta,
                                                  float* __restrict__ out, int M) {
    extern __shared__ __half smem[];
    __half* As = smem;                          // 128 x RST
    __half* Bs = smem + 128 * RST;              // 256 x RST
    float2* sred = (float2*)(smem + (128 + 256) * RST);  // [2][8][16]

    int tid = threadIdx.x;
    int wid = tid >> 5;
    int lane = tid & 31;
    int g = lane >> 2;
    int t = lane & 3;
    int mchunk = wid & 7;
    int nhalf = wid >> 3;
    int rowBase = blockIdx.x * 128;

    #pragma unroll
    for (int j = 0; j < 8; j++) {
        int l = tid + 512 * j;
        int row = l >> 5;
        int unit = l & 31;
        int4 v = make_int4(0, 0, 0, 0);
        if (rowBase + row < M)
            v = *(const int4*)(g_afeat16 + (size_t)(rowBase + row) * D + unit * 8);
        *(int4*)&As[row * RST + unit * 8] = v;
    }
    #pragma unroll
    for (int j = 0; j < 16; j++) {
        int l = tid + 512 * j;
        int row = l >> 5;
        int unit = l & 31;
        *(int4*)&Bs[row * RST + unit * 8] =
            *(const int4*)(g_w16t + (size_t)row * D + unit * 8);
    }
    __syncthreads();

    float cacc[16][4];
    #pragma unroll
    for (int i = 0; i < 16; i++)
        #pragma unroll
        for (int j = 0; j < 4; j++) cacc[i][j] = 0.f;

    // ldmatrix per-lane base addresses (bytes)
    // A x4: matrices {rows 0-7,8-15} x {k 0-7,8-15} of this warp's 16-row chunk
    uint32_t sbA = smem_u32(As);
    uint32_t sbB = smem_u32(Bs);
    uint32_t a_addr = sbA + (uint32_t)(((mchunk * 16 + (lane & 15)) * RST +
                                        ((lane >> 4) & 1) * 8) * 2);
    // B x4 per n-tile-pair p: matrices {n rows p*16+0-7, +8-15} x {k 0-7,8-15}
    uint32_t b_addr[8];
    #pragma unroll
    for (int p = 0; p < 8; p++)
        b_addr[p] = sbB + (uint32_t)(((nhalf * 128 + p * 16 + (lane & 7) +
                                       ((lane >> 4) << 3)) * RST +
                                      ((lane >> 3) & 1) * 8) * 2);

    #pragma unroll
    for (int kc = 0; kc < 16; kc++) {
        unsigned a[4];
        LDSM_X4(a[0], a[1], a[2], a[3], a_addr + kc * 32);
        #pragma unroll
        for (int p = 0; p < 8; p++) {
            unsigned b0, b1, b2, b3;
            LDSM_X4(b0, b1, b2, b3, b_addr[p] + kc * 32);
            mma16816(cacc[2 * p], a, b0, b1, cacc[2 * p]);
            mma16816(cacc[2 * p + 1], a, b2, b3, cacc[2 * p + 1]);
        }
    }

    float s0 = 0.f, ss0 = 0.f, s1 = 0.f, ss1 = 0.f;
    #pragma unroll
    for (int nt = 0; nt < 16; nt++) {
        float c0 = fmaxf(cacc[nt][0], 0.f);
        float c1 = fmaxf(cacc[nt][1], 0.f);
        float c2 = fmaxf(cacc[nt][2], 0.f);
        float c3 = fmaxf(cacc[nt][3], 0.f);
        cacc[nt][0] = c0; cacc[nt][1] = c1; cacc[nt][2] = c2; cacc[nt][3] = c3;
        s0 += c0 + c1; ss0 += c0 * c0 + c1 * c1;
        s1 += c2 + c3; ss1 += c2 * c2 + c3 * c3;
    }
    #pragma unroll
    for (int o = 1; o <= 2; o <<= 1) {
        s0 += __shfl_xor_sync(0xffffffffu, s0, o);
        ss0 += __shfl_xor_sync(0xffffffffu, ss0, o);
        s1 += __shfl_xor_sync(0xffffffffu, s1, o);
        ss1 += __shfl_xor_sync(0xffffffffu, ss1, o);
    }
    if (t == 0) {
        sred[(nhalf * 8 + mchunk) * 16 + g] = make_float2(s0, ss0);
        sred[(nhalf * 8 + mchunk) * 16 + g + 8] = make_float2(s1, ss1);
    }
    __syncthreads();
    float2 u0 = sred[(0 * 8 + mchunk) * 16 + g];
    float2 v0 = sred[(1 * 8 + mchunk) * 16 + g];
    float2 u1 = sred[(0 * 8 + mchunk) * 16 + g + 8];
    float2 v1 = sred[(1 * 8 + mchunk) * 16 + g + 8];
    float mu0 = (u0.x + v0.x) * (1.0f / D);
    float var0 = (u0.y + v0.y) * (1.0f / D) - mu0 * mu0;
    float rs0 = rsqrtf(var0 + LN_EPS);
    float mu1 = (u1.x + v1.x) * (1.0f / D);
    float var1 = (u1.y + v1.y) * (1.0f / D) - mu1 * mu1;
    float rs1 = rsqrtf(var1 + LN_EPS);

    int gr0 = rowBase + mchunk * 16 + g;
    int gr1 = gr0 + 8;
    #pragma unroll
    for (int nt = 0; nt < 16; nt++) {
        int col = nhalf * 128 + nt * 8 + 2 * t;
        float2 gm = *(const float2*)(gamma + col);
        float2 bt = *(const float2*)(beta + col);
        if (gr0 < M) {
            float2 o0;
            o0.x = (cacc[nt][0] - mu0) * rs0 * gm.x + bt.x;
            o0.y = (cacc[nt][1] - mu0) * rs0 * gm.y + bt.y;
            *(float2*)(out + (size_t)gr0 * D + col) = o0;
        }
        if (gr1 < M) {
            float2 o1;
            o1.x = (cacc[nt][2] - mu1) * rs1 * gm.x + bt.x;
            o1.y = (cacc[nt][3] - mu1) * rs1 * gm.y + bt.y;
            *(float2*)(out + (size_t)gr1 * D + col) = o1;
        }
    }
}

// ---------------- launch ----------------------------------------------------
extern "C" void kernel_launch(void* const* d_in, const int* in_sizes, int n_in,
                              void* d_out, int out_size) {
    const float* feat = (const float*)d_in[0];
    const float* W0 = (const float*)d_in[1];
    const float* W1 = (const float*)d_in[2];
    const float* W2 = (const float*)d_in[3];
    // d_in[4..6] = a0,a1,a2: softmax over size-1 tensors is identically 1,
    // so the mixing weights are always [1/3,1/3,1/3] independent of values.
    const float* gamma = (const float*)d_in[7];
    const float* beta = (const float*)d_in[8];
    const int* src0 = (const int*)d_in[9];
    const int* dst0 = (const int*)d_in[10];
    const int* src1 = (const int*)d_in[11];
    const int* dst1 = (const int*)d_in[12];
    const int* src2 = (const int*)d_in[13];
    const int* dst2 = (const int*)d_in[14];
    float* out = (float*)d_out;

    int N = in_sizes[0] / D;
    int E = in_sizes[9];
    int total2 = N * D / 2;

    static cudaStream_t s_conv = nullptr;
    static cudaEvent_t s_fork = nullptr, s_evC = nullptr;
    if (s_conv == nullptr) {
        cudaStreamCreateWithFlags(&s_conv, cudaStreamNonBlocking);
        cudaEventCreateWithFlags(&s_fork, cudaEventDisableTiming);
        cudaEventCreateWithFlags(&s_evC, cudaEventDisableTiming);
        cudaFuncSetAttribute(gemm_ln_tc,
                             cudaFuncAttributeMaxDynamicSharedMemorySize, GEMM_SMEM);
    }

    // fork: fp16 conversions run concurrently with the bucket build
    cudaEventRecord(s_fork, 0);
    cudaStreamWaitEvent(s_conv, s_fork, 0);
    conv_kernel<<<(total2 + 255) / 256, 256, 0, s_conv>>>(feat, W0, W1, W2, total2);
    cudaEventRecord(s_evC, s_conv);

    // deg starts zero (static init on first call, agg resets it every call)
    scatter_kernel<<<(3 * E + 1023) / 1024, 256>>>(src0, dst0, src1, dst1,
                                                   src2, dst2, N, E);

    // join conv, then aggregate + GEMM
    cudaStreamWaitEvent(0, s_evC, 0);
    agg_kernel<<<(N + 7) / 8, 256>>>(N);
    gemm_ln_tc<<<(N + 127) / 128, 512, GEMM_SMEM>>>(gamma, beta, out, N);
}